// round 1
// baseline (speedup 1.0000x reference)
#include <cuda_runtime.h>
#include <cstddef>

// Problem constants
// B=8, PH=PW=256, D=512, C=256, WS=8, NGRAM=2, HEADS=8, hd=32
// uni grid: 32x32 per image -> NPOS = 8*32*32 = 8192 positions

#define NPOS 8192

// Scratch (device globals; allocation is forbidden)
__device__ __align__(16) float g_wt[128 * 256];        // transposed conv weights [k][c]
__device__ __align__(16) float g_uni[NPOS * 256];      // conv output, position-major
__device__ __align__(16) float g_qkv[NPOS * 768];      // qkv per position [q|k|v]
__device__ __align__(16) float g_mfb[NPOS * 512];      // mean attn context [fwd(256) | bwd(256)]
__device__ __align__(16) float g_wcat[512 * 512];      // fused proj+merge weight [d][e]
__device__ __align__(16) float g_biasf[512];           // fused bias

// ---------------------------------------------------------------------------
// Transpose depthwise conv weights: w[c][ic][kh][kw] (c major) -> g_wt[k][c]
// with k = ic*64 + kh*8 + kw, so the conv kernel reads coalesced per step.
// ---------------------------------------------------------------------------
__global__ void wtrans_kernel(const float* __restrict__ w) {
    int idx = blockIdx.x * 256 + threadIdx.x;   // 0 .. 32767
    int c = idx >> 7;
    int kk = idx & 127;
    g_wt[kk * 256 + c] = w[idx];
}

// ---------------------------------------------------------------------------
// Depthwise conv 8x8 stride 8 (VALID). One block per output position (b,h,w),
// thread c computes output channel c from input channels (2c, 2c+1).
// x layout: [b][256][256][512] NHWC.  Each x element is read exactly once.
// ---------------------------------------------------------------------------
__global__ __launch_bounds__(256) void conv_kernel(const float* __restrict__ x,
                                                   const float* __restrict__ ub) {
    int blk = blockIdx.x;                 // b*1024 + h*32 + w
    int bb = blk >> 10;
    int h = (blk >> 5) & 31;
    int ww = blk & 31;
    int c = threadIdx.x;

    const float* xp = x + ((size_t)(bb * 256 + h * 8) * 256 + ww * 8) * 512 + 2 * c;

    float acc = 0.f;
#pragma unroll
    for (int kh = 0; kh < 8; kh++) {
#pragma unroll
        for (int kw = 0; kw < 8; kw++) {
            float2 xv = *(const float2*)(xp + ((size_t)kh * 256 + kw) * 512);
            int kidx = kh * 8 + kw;
            acc += xv.x * g_wt[kidx * 256 + c];
            acc += xv.y * g_wt[(64 + kidx) * 256 + c];
        }
    }
    g_uni[blk * 256 + c] = acc + ub[c];
}

// ---------------------------------------------------------------------------
// Generic NT SGEMM with bias: C[m][n] = sum_k A[m][k]*B[n][k] + bias[n]
// A: MxK row-major, B: NxK row-major. M%128==0, N%128==0, K%8==0 required.
// 128x128 block tile, BK=8, 256 threads, 8x8 per-thread microtile.
// ---------------------------------------------------------------------------
__global__ __launch_bounds__(256) void sgemm_nt(const float* __restrict__ A,
                                                const float* __restrict__ Bm,
                                                const float* __restrict__ bias,
                                                float* __restrict__ C,
                                                int M, int N, int K) {
    __shared__ __align__(16) float As[8][128];
    __shared__ __align__(16) float Bs[8][128];

    int bm = blockIdx.y * 128;
    int bn = blockIdx.x * 128;
    int tid = threadIdx.x;
    int tr = tid >> 4;        // 0..15
    int tc = tid & 15;        // 0..15
    int lrow = tid >> 1;      // 0..127
    int lk = (tid & 1) * 4;   // 0 or 4

    const float* Ag = A + (size_t)(bm + lrow) * K + lk;
    const float* Bg = Bm + (size_t)(bn + lrow) * K + lk;

    float acc[8][8];
#pragma unroll
    for (int i = 0; i < 8; i++)
#pragma unroll
        for (int j = 0; j < 8; j++) acc[i][j] = 0.f;

    for (int k0 = 0; k0 < K; k0 += 8) {
        float4 av = *(const float4*)(Ag + k0);
        float4 bv = *(const float4*)(Bg + k0);
        As[lk + 0][lrow] = av.x;
        As[lk + 1][lrow] = av.y;
        As[lk + 2][lrow] = av.z;
        As[lk + 3][lrow] = av.w;
        Bs[lk + 0][lrow] = bv.x;
        Bs[lk + 1][lrow] = bv.y;
        Bs[lk + 2][lrow] = bv.z;
        Bs[lk + 3][lrow] = bv.w;
        __syncthreads();

#pragma unroll
        for (int kk = 0; kk < 8; kk++) {
            float a[8], b[8];
            *(float4*)(a) = *(const float4*)&As[kk][tr * 8];
            *(float4*)(a + 4) = *(const float4*)&As[kk][tr * 8 + 4];
            *(float4*)(b) = *(const float4*)&Bs[kk][tc * 8];
            *(float4*)(b + 4) = *(const float4*)&Bs[kk][tc * 8 + 4];
#pragma unroll
            for (int i = 0; i < 8; i++)
#pragma unroll
                for (int j = 0; j < 8; j++) acc[i][j] += a[i] * b[j];
        }
        __syncthreads();
    }

    float bj[8];
#pragma unroll
    for (int j = 0; j < 8; j++) bj[j] = bias[bn + tc * 8 + j];

#pragma unroll
    for (int i = 0; i < 8; i++) {
        float* Cp = C + (size_t)(bm + tr * 8 + i) * N + bn + tc * 8;
        float4 o0 = make_float4(acc[i][0] + bj[0], acc[i][1] + bj[1],
                                acc[i][2] + bj[2], acc[i][3] + bj[3]);
        float4 o1 = make_float4(acc[i][4] + bj[4], acc[i][5] + bj[5],
                                acc[i][6] + bj[6], acc[i][7] + bj[7]);
        *(float4*)Cp = o0;
        *(float4*)(Cp + 4) = o1;
    }
}

// ---------------------------------------------------------------------------
// Attention over the 2x2 token window, both contexts, with token-mean.
// One block per grid position (512 threads = 2 ctx * 8 heads * 32 lanes).
// Token (i,j) of context fwd at (h,w) -> uni position (clamp(h+i), clamp(w+j))
//   fwd: index 32 maps to 30 (pad_fwd appends row/col 30)
//   bwd: index -1 maps to 1  (pad_bwd prepends row/col 1)
// Writes g_mfb[p][ctx*256 + head*32 + lane] = mean_n out[n].
// ---------------------------------------------------------------------------
__global__ __launch_bounds__(512) void attn_kernel(const float* __restrict__ table) {
    int p = blockIdx.x;
    int bb = p >> 10;
    int h = (p >> 5) & 31;
    int w = p & 31;
    int tid = threadIdx.x;
    int ctx = tid >> 8;
    int head = (tid >> 5) & 7;
    int lane = tid & 31;

    int rows[2], cols[2];
    if (ctx == 0) {
        rows[0] = h;
        rows[1] = (h == 31) ? 30 : h + 1;
        cols[0] = w;
        cols[1] = (w == 31) ? 30 : w + 1;
    } else {
        rows[0] = (h == 0) ? 1 : h - 1;
        rows[1] = h;
        cols[0] = (w == 0) ? 1 : w - 1;
        cols[1] = w;
    }

    float q[4], k[4], v[4];
#pragma unroll
    for (int n = 0; n < 4; n++) {
        int tp = (bb * 32 + rows[n >> 1]) * 32 + cols[n & 1];
        const float* base = g_qkv + (size_t)tp * 768 + head * 32 + lane;
        q[n] = base[0];
        k[n] = base[256];
        v[n] = base[512];
    }

    const float scale = 0.17677669529663687f;  // 1/sqrt(32)
    float s[4][4];
#pragma unroll
    for (int n = 0; n < 4; n++) {
#pragma unroll
        for (int m = 0; m < 4; m++) {
            float t = q[n] * k[m];
            t += __shfl_xor_sync(0xffffffffu, t, 16);
            t += __shfl_xor_sync(0xffffffffu, t, 8);
            t += __shfl_xor_sync(0xffffffffu, t, 4);
            t += __shfl_xor_sync(0xffffffffu, t, 2);
            t += __shfl_xor_sync(0xffffffffu, t, 1);
            int ridx = ((n >> 1) - (m >> 1) + 1) * 3 + ((n & 1) - (m & 1) + 1);
            s[n][m] = t * scale + table[ridx * 8 + head];
        }
    }

    float outd = 0.f;
#pragma unroll
    for (int n = 0; n < 4; n++) {
        float mx = fmaxf(fmaxf(s[n][0], s[n][1]), fmaxf(s[n][2], s[n][3]));
        float e0 = __expf(s[n][0] - mx);
        float e1 = __expf(s[n][1] - mx);
        float e2 = __expf(s[n][2] - mx);
        float e3 = __expf(s[n][3] - mx);
        float inv = 1.f / (e0 + e1 + e2 + e3);
        outd += (e0 * v[0] + e1 * v[1] + e2 * v[2] + e3 * v[3]) * inv;
    }
    g_mfb[(size_t)p * 512 + ctx * 256 + head * 32 + lane] = outd * 0.25f;
}

// ---------------------------------------------------------------------------
// Fuse proj into merge:
//   Wcat[d][e<256]   = sum_c merge_w[d][c]     * proj_w[c][e]
//   Wcat[d][256+e]   = sum_c merge_w[d][256+c] * proj_w[c][e]
//   biasf[d] = merge_b[d] + sum_c proj_b[c]*(merge_w[d][c]+merge_w[d][256+c])
// ---------------------------------------------------------------------------
__global__ __launch_bounds__(512) void fuse_w_kernel(const float* __restrict__ mw,
                                                     const float* __restrict__ pw) {
    int d = blockIdx.x;
    int e = threadIdx.x;
    int eh = e & 255;
    int half = e >> 8;
    const float* mrow = mw + d * 512 + half * 256;
    float acc = 0.f;
#pragma unroll 4
    for (int cc = 0; cc < 256; cc++) acc += mrow[cc] * pw[cc * 256 + eh];
    g_wcat[d * 512 + e] = acc;
}

__global__ void fuse_bias_kernel(const float* __restrict__ mw,
                                 const float* __restrict__ pb,
                                 const float* __restrict__ mb) {
    int d = blockIdx.x * blockDim.x + threadIdx.x;
    if (d >= 512) return;
    float acc = mb[d];
    for (int cc = 0; cc < 256; cc++)
        acc += pb[cc] * (mw[d * 512 + cc] + mw[d * 512 + 256 + cc]);
    g_biasf[d] = acc;
}

// ---------------------------------------------------------------------------
// Launch
// Inputs (metadata order): x, unigram_w, unigram_b, qkv_w, qkv_b,
//   rel_bias_table, proj_w, proj_b, merge_w, merge_b, ngram
// Output: (8,32,32,1,1,512) float32 -> contiguous [8192][512]
// ---------------------------------------------------------------------------
extern "C" void kernel_launch(void* const* d_in, const int* in_sizes, int n_in,
                              void* d_out, int out_size) {
    const float* x     = (const float*)d_in[0];
    const float* uw    = (const float*)d_in[1];
    const float* ub    = (const float*)d_in[2];
    const float* qkvw  = (const float*)d_in[3];
    const float* qkvb  = (const float*)d_in[4];
    const float* table = (const float*)d_in[5];
    const float* pw    = (const float*)d_in[6];
    const float* pb    = (const float*)d_in[7];
    const float* mw    = (const float*)d_in[8];
    const float* mb    = (const float*)d_in[9];
    float* out = (float*)d_out;

    float *uni, *qkv, *mfb, *wcat, *biasf;
    cudaGetSymbolAddress((void**)&uni, g_uni);
    cudaGetSymbolAddress((void**)&qkv, g_qkv);
    cudaGetSymbolAddress((void**)&mfb, g_mfb);
    cudaGetSymbolAddress((void**)&wcat, g_wcat);
    cudaGetSymbolAddress((void**)&biasf, g_biasf);

    // weight transpose + fused proj/merge weights (independent of main chain)
    wtrans_kernel<<<128, 256>>>(uw);
    fuse_w_kernel<<<512, 512>>>(mw, pw);
    fuse_bias_kernel<<<2, 256>>>(mw, pb, mb);

    // main chain
    conv_kernel<<<8192, 256>>>(x, ub);
    sgemm_nt<<<dim3(768 / 128, 8192 / 128), 256>>>(uni, qkvw, qkvb, qkv,
                                                   8192, 768, 256);
    attn_kernel<<<8192, 512>>>(table);
    sgemm_nt<<<dim3(512 / 128, 8192 / 128), 256>>>(mfb, wcat, biasf, out,
                                                   8192, 512, 512);
}

// round 7
// speedup vs baseline: 1.2921x; 1.2921x over previous
#include <cuda_runtime.h>
#include <cuda_bf16.h>
#include <cstdint>
#include <cstddef>

// B=8, PH=PW=256, D=512, C=256, WS=8, NGRAM=2, HEADS=8, hd=32
// uni grid: 32x32 per image -> NPOS = 8*32*32 = 8192 positions
#define NPOS 8192

// Scratch (device globals; allocation is forbidden)
__device__ __align__(16) float g_wt[128 * 256];   // transposed conv weights [k][c]
__device__ __align__(16) float g_qkv[NPOS * 768]; // qkv per position [q|k|v] fp32
__device__ __align__(16) float g_biasf[512];      // fused bias

// bf16 split planes (hi/lo) for emulated-fp32 GEMM operands
__device__ __align__(16) __nv_bfloat16 g_uA_hi[NPOS * 256];  // uni (GEMM1 A)
__device__ __align__(16) __nv_bfloat16 g_uA_lo[NPOS * 256];
__device__ __align__(16) __nv_bfloat16 g_wq_hi[768 * 256];   // qkv_w (GEMM1 B)
__device__ __align__(16) __nv_bfloat16 g_wq_lo[768 * 256];
__device__ __align__(16) __nv_bfloat16 g_mf_hi[NPOS * 512];  // mfb (GEMM2 A)
__device__ __align__(16) __nv_bfloat16 g_mf_lo[NPOS * 512];
__device__ __align__(16) __nv_bfloat16 g_wc_hi[512 * 512];   // wcat (GEMM2 B)
__device__ __align__(16) __nv_bfloat16 g_wc_lo[512 * 512];

// ===========================================================================
// helpers
// ===========================================================================
__device__ __forceinline__ uint32_t smem_u32(const void* p) {
    uint32_t a;
    asm("{ .reg .u64 t; cvta.to.shared.u64 t, %1; cvt.u32.u64 %0, t; }"
        : "=r"(a) : "l"(p));
    return a;
}
__device__ __forceinline__ void cp_async16(uint32_t saddr, const void* g) {
    asm volatile("cp.async.cg.shared.global [%0], [%1], 16;" :: "r"(saddr), "l"(g));
}
__device__ __forceinline__ void cp_commit() {
    asm volatile("cp.async.commit_group;" ::: "memory");
}
__device__ __forceinline__ void cp_wait1() {
    asm volatile("cp.async.wait_group 1;" ::: "memory");
}
__device__ __forceinline__ void cp_wait0() {
    asm volatile("cp.async.wait_group 0;" ::: "memory");
}
// m16n8k16 bf16 MMA, fp32 accumulate
__device__ __forceinline__ void mma_bf16(float* c, const uint32_t* a, const uint32_t* b) {
    asm volatile(
        "mma.sync.aligned.m16n8k16.row.col.f32.bf16.bf16.f32 "
        "{%0,%1,%2,%3}, {%4,%5,%6,%7}, {%8,%9}, {%0,%1,%2,%3};"
        : "+f"(c[0]), "+f"(c[1]), "+f"(c[2]), "+f"(c[3])
        : "r"(a[0]), "r"(a[1]), "r"(a[2]), "r"(a[3]), "r"(b[0]), "r"(b[1]));
}
__device__ __forceinline__ void split_bf16(float v, __nv_bfloat16* hi, __nv_bfloat16* lo) {
    __nv_bfloat16 h = __float2bfloat16(v);
    *hi = h;
    *lo = __float2bfloat16(v - __bfloat162float(h));
}

// ===========================================================================
// prep: transpose conv weights; split qkv_w into bf16 planes
// ===========================================================================
__global__ void wtrans_kernel(const float* __restrict__ w) {
    int idx = blockIdx.x * 256 + threadIdx.x;
    int c = idx >> 7;
    int kk = idx & 127;
    g_wt[kk * 256 + c] = w[idx];
}

__global__ void wq_split_kernel(const float* __restrict__ w) {
    int idx = blockIdx.x * 256 + threadIdx.x;  // 768*256 elems
    split_bf16(w[idx], &g_wq_hi[idx], &g_wq_lo[idx]);
}

// ===========================================================================
// Depthwise conv 8x8 stride 8 (VALID). HBM-roofline bound (87.7% DRAM).
// Epilogue writes bf16 hi/lo planes for GEMM1 A.
// ===========================================================================
__global__ __launch_bounds__(256) void conv_kernel(const float* __restrict__ x,
                                                   const float* __restrict__ ub) {
    int blk = blockIdx.x;
    int bb = blk >> 10;
    int h = (blk >> 5) & 31;
    int ww = blk & 31;
    int c = threadIdx.x;

    const float* xp = x + ((size_t)(bb * 256 + h * 8) * 256 + ww * 8) * 512 + 2 * c;

    float acc = 0.f;
#pragma unroll
    for (int kh = 0; kh < 8; kh++) {
#pragma unroll
        for (int kw = 0; kw < 8; kw++) {
            float2 xv = *(const float2*)(xp + ((size_t)kh * 256 + kw) * 512);
            int kidx = kh * 8 + kw;
            acc += xv.x * g_wt[kidx * 256 + c];
            acc += xv.y * g_wt[(64 + kidx) * 256 + c];
        }
    }
    split_bf16(acc + ub[c], &g_uA_hi[blk * 256 + c], &g_uA_lo[blk * 256 + c]);
}

// ===========================================================================
// Emulated-fp32 NT GEMM via bf16x2 split (3 MMAs: hi*hi + hi*lo + lo*hi):
//   C[m][n] = sum_k A[m][k]*B[n][k] + bias[n]
// A,B given as bf16 hi/lo planes, row-major [.][K]. C fp32.
// 128x128 CTA tile, BK=32, double-buffered cp.async, 8 warps (2x4), 64x32/warp.
// SMEM: per buffer 4 planes (Ah,Al,Bh,Bl), each 128 rows x 40 bf16 pitch.
// Requirements: M%128==0, N%128==0, K%32==0.
// ===========================================================================
#define PITCHW 20                       // words (u32) per row = 40 bf16
#define PLANE_B (128 * PITCHW * 4)      // bytes per plane = 10240
#define BUF_B (4 * PLANE_B)             // bytes per buffer = 40960
#define TB_SMEM (2 * BUF_B)             // 81920 bytes

__global__ __launch_bounds__(256, 1) void bgemm_x2(const __nv_bfloat16* __restrict__ Ah,
                                                   const __nv_bfloat16* __restrict__ Al,
                                                   const __nv_bfloat16* __restrict__ Bh,
                                                   const __nv_bfloat16* __restrict__ Bl,
                                                   const float* __restrict__ bias,
                                                   float* __restrict__ C,
                                                   int K, int N) {
    extern __shared__ __align__(16) uint32_t smemw[];
    uint32_t sbase = smem_u32(smemw);

    int tid = threadIdx.x;
    int wid = tid >> 5;
    int lane = tid & 31;
    int g = lane >> 2;      // 0..7
    int tg = lane & 3;      // 0..3
    int warp_m = wid >> 2;  // 0..1
    int warp_n = wid & 3;   // 0..3

    int bm = blockIdx.y * 128;
    int bn = blockIdx.x * 128;

    // copy geometry: row = tid/2, half = tid&1 covers 16 bf16 (32B)
    int row = tid >> 1;
    int half = tid & 1;
    const __nv_bfloat16* gAh = Ah + (size_t)(bm + row) * K + half * 16;
    const __nv_bfloat16* gAl = Al + (size_t)(bm + row) * K + half * 16;
    const __nv_bfloat16* gBh = Bh + (size_t)(bn + row) * K + half * 16;
    const __nv_bfloat16* gBl = Bl + (size_t)(bn + row) * K + half * 16;
    uint32_t dst0 = sbase + (uint32_t)(row * PITCHW * 4 + half * 32);

    int nchunks = K >> 5;

#define LOAD_CHUNK(ci)                                                    \
    {                                                                     \
        uint32_t _o = ((ci) & 1) * BUF_B;                                 \
        int _k = (ci) * 32;                                               \
        cp_async16(dst0 + _o,                     gAh + _k);              \
        cp_async16(dst0 + _o + 16,                gAh + _k + 8);          \
        cp_async16(dst0 + _o + PLANE_B,           gAl + _k);              \
        cp_async16(dst0 + _o + PLANE_B + 16,      gAl + _k + 8);          \
        cp_async16(dst0 + _o + 2 * PLANE_B,       gBh + _k);              \
        cp_async16(dst0 + _o + 2 * PLANE_B + 16,  gBh + _k + 8);          \
        cp_async16(dst0 + _o + 3 * PLANE_B,       gBl + _k);              \
        cp_async16(dst0 + _o + 3 * PLANE_B + 16,  gBl + _k + 8);          \
        cp_commit();                                                      \
    }

    float c[4][4][4];
#pragma unroll
    for (int mt = 0; mt < 4; mt++)
#pragma unroll
        for (int nt = 0; nt < 4; nt++)
#pragma unroll
            for (int e = 0; e < 4; e++) c[mt][nt][e] = 0.f;

    LOAD_CHUNK(0);

    for (int i = 0; i < nchunks; i++) {
        if (i + 1 < nchunks) {
            LOAD_CHUNK(i + 1);
            cp_wait1();
        } else {
            cp_wait0();
        }
        __syncthreads();

        const uint32_t* wb = smemw + (i & 1) * (BUF_B / 4);
        const uint32_t* AH = wb + (warp_m * 64) * PITCHW;
        const uint32_t* AL = AH + PLANE_B / 4;
        const uint32_t* BH = wb + 2 * (PLANE_B / 4) + (warp_n * 32) * PITCHW;
        const uint32_t* BL = BH + PLANE_B / 4;

#pragma unroll
        for (int ks = 0; ks < 2; ks++) {
            int kw = ks * 8 + tg;
            uint32_t ah[4][4], bh[4][2], bl[4][2];
#pragma unroll
            for (int mt = 0; mt < 4; mt++) {
                const uint32_t* ap = AH + (mt * 16 + g) * PITCHW + kw;
                ah[mt][0] = ap[0];
                ah[mt][1] = ap[8 * PITCHW];
                ah[mt][2] = ap[4];
                ah[mt][3] = ap[8 * PITCHW + 4];
            }
#pragma unroll
            for (int nt = 0; nt < 4; nt++) {
                const uint32_t* bp = BH + (nt * 8 + g) * PITCHW + kw;
                bh[nt][0] = bp[0];
                bh[nt][1] = bp[4];
            }
            // hi * hi
#pragma unroll
            for (int mt = 0; mt < 4; mt++)
#pragma unroll
                for (int nt = 0; nt < 4; nt++) mma_bf16(c[mt][nt], ah[mt], bh[nt]);
            // hi * lo
#pragma unroll
            for (int nt = 0; nt < 4; nt++) {
                const uint32_t* bp = BL + (nt * 8 + g) * PITCHW + kw;
                bl[nt][0] = bp[0];
                bl[nt][1] = bp[4];
            }
#pragma unroll
            for (int mt = 0; mt < 4; mt++)
#pragma unroll
                for (int nt = 0; nt < 4; nt++) mma_bf16(c[mt][nt], ah[mt], bl[nt]);
            // lo * hi
#pragma unroll
            for (int mt = 0; mt < 4; mt++) {
                const uint32_t* ap = AL + (mt * 16 + g) * PITCHW + kw;
                ah[mt][0] = ap[0];
                ah[mt][1] = ap[8 * PITCHW];
                ah[mt][2] = ap[4];
                ah[mt][3] = ap[8 * PITCHW + 4];
            }
#pragma unroll
            for (int mt = 0; mt < 4; mt++)
#pragma unroll
                for (int nt = 0; nt < 4; nt++) mma_bf16(c[mt][nt], ah[mt], bh[nt]);
        }
        __syncthreads();
    }
#undef LOAD_CHUNK

    // epilogue: direct stores with bias
#pragma unroll
    for (int nt = 0; nt < 4; nt++) {
        int col = bn + warp_n * 32 + nt * 8 + 2 * tg;
        float2 bv = *(const float2*)(bias + col);
#pragma unroll
        for (int mt = 0; mt < 4; mt++) {
            int r0 = bm + warp_m * 64 + mt * 16 + g;
            float2 v0 = make_float2(c[mt][nt][0] + bv.x, c[mt][nt][1] + bv.y);
            float2 v1 = make_float2(c[mt][nt][2] + bv.x, c[mt][nt][3] + bv.y);
            *(float2*)(C + (size_t)r0 * N + col) = v0;
            *(float2*)(C + (size_t)(r0 + 8) * N + col) = v1;
        }
    }
}

// ===========================================================================
// Attention over the 2x2 token window, both contexts, with token-mean.
// Writes bf16 hi/lo planes for GEMM2 A.
// ===========================================================================
__global__ __launch_bounds__(512) void attn_kernel(const float* __restrict__ table) {
    int p = blockIdx.x;
    int bb = p >> 10;
    int h = (p >> 5) & 31;
    int w = p & 31;
    int tid = threadIdx.x;
    int ctx = tid >> 8;
    int head = (tid >> 5) & 7;
    int lane = tid & 31;

    int rows[2], cols[2];
    if (ctx == 0) {
        rows[0] = h;
        rows[1] = (h == 31) ? 30 : h + 1;
        cols[0] = w;
        cols[1] = (w == 31) ? 30 : w + 1;
    } else {
        rows[0] = (h == 0) ? 1 : h - 1;
        rows[1] = h;
        cols[0] = (w == 0) ? 1 : w - 1;
        cols[1] = w;
    }

    float q[4], k[4], v[4];
#pragma unroll
    for (int n = 0; n < 4; n++) {
        int tp = (bb * 32 + rows[n >> 1]) * 32 + cols[n & 1];
        const float* base = g_qkv + (size_t)tp * 768 + head * 32 + lane;
        q[n] = base[0];
        k[n] = base[256];
        v[n] = base[512];
    }

    const float scale = 0.17677669529663687f;
    float s[4][4];
#pragma unroll
    for (int n = 0; n < 4; n++) {
#pragma unroll
        for (int m = 0; m < 4; m++) {
            float t = q[n] * k[m];
            t += __shfl_xor_sync(0xffffffffu, t, 16);
            t += __shfl_xor_sync(0xffffffffu, t, 8);
            t += __shfl_xor_sync(0xffffffffu, t, 4);
            t += __shfl_xor_sync(0xffffffffu, t, 2);
            t += __shfl_xor_sync(0xffffffffu, t, 1);
            int ridx = ((n >> 1) - (m >> 1) + 1) * 3 + ((n & 1) - (m & 1) + 1);
            s[n][m] = t * scale + table[ridx * 8 + head];
        }
    }

    float outd = 0.f;
#pragma unroll
    for (int n = 0; n < 4; n++) {
        float mx = fmaxf(fmaxf(s[n][0], s[n][1]), fmaxf(s[n][2], s[n][3]));
        float e0 = __expf(s[n][0] - mx);
        float e1 = __expf(s[n][1] - mx);
        float e2 = __expf(s[n][2] - mx);
        float e3 = __expf(s[n][3] - mx);
        float inv = 1.f / (e0 + e1 + e2 + e3);
        outd += (e0 * v[0] + e1 * v[1] + e2 * v[2] + e3 * v[3]) * inv;
    }
    int o = p * 512 + ctx * 256 + head * 32 + lane;
    split_bf16(outd * 0.25f, &g_mf_hi[o], &g_mf_lo[o]);
}

// ===========================================================================
// Fuse proj into merge; emit bf16 hi/lo planes for GEMM2 B.
// ===========================================================================
__global__ __launch_bounds__(512) void fuse_w_kernel(const float* __restrict__ mw,
                                                     const float* __restrict__ pw) {
    int d = blockIdx.x;
    int e = threadIdx.x;
    int eh = e & 255;
    int half = e >> 8;
    const float* mrow = mw + d * 512 + half * 256;
    float acc = 0.f;
#pragma unroll 4
    for (int cc = 0; cc < 256; cc++) acc += mrow[cc] * pw[cc * 256 + eh];
    split_bf16(acc, &g_wc_hi[d * 512 + e], &g_wc_lo[d * 512 + e]);
}

__global__ void fuse_bias_kernel(const float* __restrict__ mw,
                                 const float* __restrict__ pb,
                                 const float* __restrict__ mb) {
    int d = blockIdx.x * blockDim.x + threadIdx.x;
    if (d >= 512) return;
    float acc = mb[d];
    for (int cc = 0; cc < 256; cc++)
        acc += pb[cc] * (mw[d * 512 + cc] + mw[d * 512 + 256 + cc]);
    g_biasf[d] = acc;
}

// ===========================================================================
// Launch
// ===========================================================================
extern "C" void kernel_launch(void* const* d_in, const int* in_sizes, int n_in,
                              void* d_out, int out_size) {
    const float* x     = (const float*)d_in[0];
    const float* uw    = (const float*)d_in[1];
    const float* ub    = (const float*)d_in[2];
    const float* qkvw  = (const float*)d_in[3];
    const float* qkvb  = (const float*)d_in[4];
    const float* table = (const float*)d_in[5];
    const float* pw    = (const float*)d_in[6];
    const float* pb    = (const float*)d_in[7];
    const float* mw    = (const float*)d_in[8];
    const float* mb    = (const float*)d_in[9];
    float* out = (float*)d_out;

    float* qkv;
    float* biasf;
    __nv_bfloat16 *uAh, *uAl, *wqh, *wql, *mfh, *mfl, *wch, *wcl;
    cudaGetSymbolAddress((void**)&qkv, g_qkv);
    cudaGetSymbolAddress((void**)&biasf, g_biasf);
    cudaGetSymbolAddress((void**)&uAh, g_uA_hi);
    cudaGetSymbolAddress((void**)&uAl, g_uA_lo);
    cudaGetSymbolAddress((void**)&wqh, g_wq_hi);
    cudaGetSymbolAddress((void**)&wql, g_wq_lo);
    cudaGetSymbolAddress((void**)&mfh, g_mf_hi);
    cudaGetSymbolAddress((void**)&mfl, g_mf_lo);
    cudaGetSymbolAddress((void**)&wch, g_wc_hi);
    cudaGetSymbolAddress((void**)&wcl, g_wc_lo);

    cudaFuncSetAttribute(bgemm_x2, cudaFuncAttributeMaxDynamicSharedMemorySize,
                         TB_SMEM);

    // prep kernels (independent of main chain)
    wtrans_kernel<<<128, 256>>>(uw);
    wq_split_kernel<<<768, 256>>>(qkvw);
    fuse_w_kernel<<<512, 512>>>(mw, pw);
    fuse_bias_kernel<<<2, 256>>>(mw, pb, mb);

    // main chain
    conv_kernel<<<8192, 256>>>(x, ub);
    bgemm_x2<<<dim3(768 / 128, 8192 / 128), 256, TB_SMEM>>>(uAh, uAl, wqh, wql,
                                                            qkvb, qkv, 256, 768);
    attn_kernel<<<8192, 512>>>(table);
    bgemm_x2<<<dim3(512 / 128, 8192 / 128), 256, TB_SMEM>>>(mfh, mfl, wch, wcl,
                                                            biasf, out, 512, 512);
}

// round 9
// speedup vs baseline: 1.5541x; 1.2028x over previous
#include <cuda_runtime.h>
#include <cuda_bf16.h>
#include <cstdint>
#include <cstddef>

// B=8, PH=PW=256, D=512, C=256, WS=8, NGRAM=2, HEADS=8, hd=32
// uni grid: 32x32 per image -> NPOS = 8*32*32 = 8192 positions
#define NPOS 8192

// Scratch (device globals; allocation is forbidden)
__device__ __align__(16) float g_wt[128 * 256];   // transposed conv weights [k][c]
__device__ __align__(16) float g_qkv[NPOS * 768]; // qkv per position [q|k|v] fp32
__device__ __align__(16) float g_biasf[512];      // fused bias

// bf16 split planes (hi/lo) for emulated-fp32 GEMM operands
__device__ __align__(16) __nv_bfloat16 g_uA_hi[NPOS * 256];  // uni (GEMM1 A)
__device__ __align__(16) __nv_bfloat16 g_uA_lo[NPOS * 256];
__device__ __align__(16) __nv_bfloat16 g_wq_hi[768 * 256];   // qkv_w (GEMM1 B)
__device__ __align__(16) __nv_bfloat16 g_wq_lo[768 * 256];
__device__ __align__(16) __nv_bfloat16 g_mf_hi[NPOS * 512];  // mfb (GEMM2 A)
__device__ __align__(16) __nv_bfloat16 g_mf_lo[NPOS * 512];
__device__ __align__(16) __nv_bfloat16 g_wc_hi[512 * 512];   // wcat (GEMM2 B)
__device__ __align__(16) __nv_bfloat16 g_wc_lo[512 * 512];

// ===========================================================================
// helpers
// ===========================================================================
__device__ __forceinline__ uint32_t smem_u32(const void* p) {
    uint32_t a;
    asm("{ .reg .u64 t; cvta.to.shared.u64 t, %1; cvt.u32.u64 %0, t; }"
        : "=r"(a) : "l"(p));
    return a;
}
__device__ __forceinline__ void cp_async16(uint32_t saddr, const void* g) {
    asm volatile("cp.async.cg.shared.global [%0], [%1], 16;" :: "r"(saddr), "l"(g));
}
__device__ __forceinline__ void cp_commit() {
    asm volatile("cp.async.commit_group;" ::: "memory");
}
__device__ __forceinline__ void cp_wait1() {
    asm volatile("cp.async.wait_group 1;" ::: "memory");
}
__device__ __forceinline__ void cp_wait0() {
    asm volatile("cp.async.wait_group 0;" ::: "memory");
}
// m16n8k16 bf16 MMA, fp32 accumulate
__device__ __forceinline__ void mma_bf16(float* c, const uint32_t* a, const uint32_t* b) {
    asm volatile(
        "mma.sync.aligned.m16n8k16.row.col.f32.bf16.bf16.f32 "
        "{%0,%1,%2,%3}, {%4,%5,%6,%7}, {%8,%9}, {%0,%1,%2,%3};"
        : "+f"(c[0]), "+f"(c[1]), "+f"(c[2]), "+f"(c[3])
        : "r"(a[0]), "r"(a[1]), "r"(a[2]), "r"(a[3]), "r"(b[0]), "r"(b[1]));
}
__device__ __forceinline__ void split_bf16(float v, __nv_bfloat16* hi, __nv_bfloat16* lo) {
    __nv_bfloat16 h = __float2bfloat16(v);
    *hi = h;
    *lo = __float2bfloat16(v - __bfloat162float(h));
}

// ===========================================================================
// prep: transpose conv weights; split qkv_w into bf16 planes
// ===========================================================================
__global__ void wtrans_kernel(const float* __restrict__ w) {
    int idx = blockIdx.x * 256 + threadIdx.x;
    int c = idx >> 7;
    int kk = idx & 127;
    g_wt[kk * 256 + c] = w[idx];
}

__global__ void wq_split_kernel(const float* __restrict__ w) {
    int idx = blockIdx.x * 256 + threadIdx.x;  // 768*256 elems
    split_bf16(w[idx], &g_wq_hi[idx], &g_wq_lo[idx]);
}

// ===========================================================================
// Depthwise conv 8x8 stride 8 (VALID). 8 w-positions per block so each
// weight value loaded once per block is reused 8x (weight DRAM refetch fix).
// grid = 1024: blk = b*128 + h*4 + wg  (wg covers w = wg*8 .. wg*8+7)
// ===========================================================================
__global__ __launch_bounds__(256) void conv_kernel(const float* __restrict__ x,
                                                   const float* __restrict__ ub) {
    int blk = blockIdx.x;
    int bb = blk >> 7;
    int h = (blk >> 2) & 31;
    int wg = blk & 3;
    int c = threadIdx.x;

    const float* xp =
        x + ((size_t)(bb * 256 + h * 8) * 256 + wg * 64) * 512 + 2 * c;

    float acc[8];
#pragma unroll
    for (int p = 0; p < 8; p++) acc[p] = 0.f;

#pragma unroll
    for (int kh = 0; kh < 8; kh++) {
#pragma unroll
        for (int kw = 0; kw < 8; kw++) {
            int kidx = kh * 8 + kw;
            float w0 = g_wt[kidx * 256 + c];
            float w1 = g_wt[(64 + kidx) * 256 + c];
            const float* row = xp + ((size_t)kh * 256 + kw) * 512;
#pragma unroll
            for (int p = 0; p < 8; p++) {
                float2 xv = *(const float2*)(row + (size_t)p * 8 * 512);
                acc[p] += xv.x * w0 + xv.y * w1;
            }
        }
    }

    float b = ub[c];
    int pos0 = (bb * 32 + h) * 32 + wg * 8;
#pragma unroll
    for (int p = 0; p < 8; p++) {
        int o = (pos0 + p) * 256 + c;
        split_bf16(acc[p] + b, &g_uA_hi[o], &g_uA_lo[o]);
    }
}

// ===========================================================================
// Emulated-fp32 NT GEMM via bf16x2 split (3 MMAs: hi*hi + hi*lo + lo*hi):
//   C[m][n] = sum_k A[m][k]*B[n][k] + bias[n]
// A,B given as bf16 hi/lo planes, row-major [.][K]. C fp32.
// 128x128 CTA tile, BK=32, double-buffered cp.async, 8 warps (2x4), 64x32/warp.
// SMEM: per buffer 4 planes (Ah,Al,Bh,Bl), each 128 rows x 40 bf16 pitch.
// Requirements: M%128==0, N%128==0, K%32==0.
// ===========================================================================
#define PITCHW 20                       // words (u32) per row = 40 bf16
#define PLANE_B (128 * PITCHW * 4)      // bytes per plane = 10240
#define BUF_B (4 * PLANE_B)             // bytes per buffer = 40960
#define TB_SMEM (2 * BUF_B)             // 81920 bytes

__global__ __launch_bounds__(256, 2) void bgemm_x2(const __nv_bfloat16* __restrict__ Ah,
                                                   const __nv_bfloat16* __restrict__ Al,
                                                   const __nv_bfloat16* __restrict__ Bh,
                                                   const __nv_bfloat16* __restrict__ Bl,
                                                   const float* __restrict__ bias,
                                                   float* __restrict__ C,
                                                   int K, int N) {
    extern __shared__ __align__(16) uint32_t smemw[];
    uint32_t sbase = smem_u32(smemw);

    int tid = threadIdx.x;
    int wid = tid >> 5;
    int lane = tid & 31;
    int g = lane >> 2;      // 0..7
    int tg = lane & 3;      // 0..3
    int warp_m = wid >> 2;  // 0..1
    int warp_n = wid & 3;   // 0..3

    int bm = blockIdx.y * 128;
    int bn = blockIdx.x * 128;

    // copy geometry: row = tid/2, half = tid&1 covers 16 bf16 (32B)
    int row = tid >> 1;
    int half = tid & 1;
    const __nv_bfloat16* gAh = Ah + (size_t)(bm + row) * K + half * 16;
    const __nv_bfloat16* gAl = Al + (size_t)(bm + row) * K + half * 16;
    const __nv_bfloat16* gBh = Bh + (size_t)(bn + row) * K + half * 16;
    const __nv_bfloat16* gBl = Bl + (size_t)(bn + row) * K + half * 16;
    uint32_t dst0 = sbase + (uint32_t)(row * PITCHW * 4 + half * 32);

    int nchunks = K >> 5;

#define LOAD_CHUNK(ci)                                                    \
    {                                                                     \
        uint32_t _o = ((ci) & 1) * BUF_B;                                 \
        int _k = (ci) * 32;                                               \
        cp_async16(dst0 + _o,                     gAh + _k);              \
        cp_async16(dst0 + _o + 16,                gAh + _k + 8);          \
        cp_async16(dst0 + _o + PLANE_B,           gAl + _k);              \
        cp_async16(dst0 + _o + PLANE_B + 16,      gAl + _k + 8);          \
        cp_async16(dst0 + _o + 2 * PLANE_B,       gBh + _k);              \
        cp_async16(dst0 + _o + 2 * PLANE_B + 16,  gBh + _k + 8);          \
        cp_async16(dst0 + _o + 3 * PLANE_B,       gBl + _k);              \
        cp_async16(dst0 + _o + 3 * PLANE_B + 16,  gBl + _k + 8);          \
        cp_commit();                                                      \
    }

    float c[4][4][4];
#pragma unroll
    for (int mt = 0; mt < 4; mt++)
#pragma unroll
        for (int nt = 0; nt < 4; nt++)
#pragma unroll
            for (int e = 0; e < 4; e++) c[mt][nt][e] = 0.f;

    LOAD_CHUNK(0);

    for (int i = 0; i < nchunks; i++) {
        if (i + 1 < nchunks) {
            LOAD_CHUNK(i + 1);
            cp_wait1();
        } else {
            cp_wait0();
        }
        __syncthreads();

        const uint32_t* wb = smemw + (i & 1) * (BUF_B / 4);
        const uint32_t* AH = wb + (warp_m * 64) * PITCHW;
        const uint32_t* AL = AH + PLANE_B / 4;
        const uint32_t* BH = wb + 2 * (PLANE_B / 4) + (warp_n * 32) * PITCHW;
        const uint32_t* BL = BH + PLANE_B / 4;

#pragma unroll
        for (int ks = 0; ks < 2; ks++) {
            int kw = ks * 8 + tg;
            uint32_t ah[4][4], bh[4][2], bl[4][2];
#pragma unroll
            for (int mt = 0; mt < 4; mt++) {
                const uint32_t* ap = AH + (mt * 16 + g) * PITCHW + kw;
                ah[mt][0] = ap[0];
                ah[mt][1] = ap[8 * PITCHW];
                ah[mt][2] = ap[4];
                ah[mt][3] = ap[8 * PITCHW + 4];
            }
#pragma unroll
            for (int nt = 0; nt < 4; nt++) {
                const uint32_t* bp = BH + (nt * 8 + g) * PITCHW + kw;
                bh[nt][0] = bp[0];
                bh[nt][1] = bp[4];
            }
            // hi * hi
#pragma unroll
            for (int mt = 0; mt < 4; mt++)
#pragma unroll
                for (int nt = 0; nt < 4; nt++) mma_bf16(c[mt][nt], ah[mt], bh[nt]);
            // hi * lo
#pragma unroll
            for (int nt = 0; nt < 4; nt++) {
                const uint32_t* bp = BL + (nt * 8 + g) * PITCHW + kw;
                bl[nt][0] = bp[0];
                bl[nt][1] = bp[4];
            }
#pragma unroll
            for (int mt = 0; mt < 4; mt++)
#pragma unroll
                for (int nt = 0; nt < 4; nt++) mma_bf16(c[mt][nt], ah[mt], bl[nt]);
            // lo * hi
#pragma unroll
            for (int mt = 0; mt < 4; mt++) {
                const uint32_t* ap = AL + (mt * 16 + g) * PITCHW + kw;
                ah[mt][0] = ap[0];
                ah[mt][1] = ap[8 * PITCHW];
                ah[mt][2] = ap[4];
                ah[mt][3] = ap[8 * PITCHW + 4];
            }
#pragma unroll
            for (int mt = 0; mt < 4; mt++)
#pragma unroll
                for (int nt = 0; nt < 4; nt++) mma_bf16(c[mt][nt], ah[mt], bh[nt]);
        }
        __syncthreads();
    }
#undef LOAD_CHUNK

    // epilogue: direct stores with bias
#pragma unroll
    for (int nt = 0; nt < 4; nt++) {
        int col = bn + warp_n * 32 + nt * 8 + 2 * tg;
        float2 bv = *(const float2*)(bias + col);
#pragma unroll
        for (int mt = 0; mt < 4; mt++) {
            int r0 = bm + warp_m * 64 + mt * 16 + g;
            float2 v0 = make_float2(c[mt][nt][0] + bv.x, c[mt][nt][1] + bv.y);
            float2 v1 = make_float2(c[mt][nt][2] + bv.x, c[mt][nt][3] + bv.y);
            *(float2*)(C + (size_t)r0 * N + col) = v0;
            *(float2*)(C + (size_t)(r0 + 8) * N + col) = v1;
        }
    }
}

// ===========================================================================
// Attention over the 2x2 token window, both contexts, with token-mean.
// Writes bf16 hi/lo planes for GEMM2 A.
// ===========================================================================
__global__ __launch_bounds__(512) void attn_kernel(const float* __restrict__ table) {
    int p = blockIdx.x;
    int bb = p >> 10;
    int h = (p >> 5) & 31;
    int w = p & 31;
    int tid = threadIdx.x;
    int ctx = tid >> 8;
    int head = (tid >> 5) & 7;
    int lane = tid & 31;

    int rows[2], cols[2];
    if (ctx == 0) {
        rows[0] = h;
        rows[1] = (h == 31) ? 30 : h + 1;
        cols[0] = w;
        cols[1] = (w == 31) ? 30 : w + 1;
    } else {
        rows[0] = (h == 0) ? 1 : h - 1;
        rows[1] = h;
        cols[0] = (w == 0) ? 1 : w - 1;
        cols[1] = w;
    }

    float q[4], k[4], v[4];
#pragma unroll
    for (int n = 0; n < 4; n++) {
        int tp = (bb * 32 + rows[n >> 1]) * 32 + cols[n & 1];
        const float* base = g_qkv + (size_t)tp * 768 + head * 32 + lane;
        q[n] = base[0];
        k[n] = base[256];
        v[n] = base[512];
    }

    const float scale = 0.17677669529663687f;
    float s[4][4];
#pragma unroll
    for (int n = 0; n < 4; n++) {
#pragma unroll
        for (int m = 0; m < 4; m++) {
            float t = q[n] * k[m];
            t += __shfl_xor_sync(0xffffffffu, t, 16);
            t += __shfl_xor_sync(0xffffffffu, t, 8);
            t += __shfl_xor_sync(0xffffffffu, t, 4);
            t += __shfl_xor_sync(0xffffffffu, t, 2);
            t += __shfl_xor_sync(0xffffffffu, t, 1);
            int ridx = ((n >> 1) - (m >> 1) + 1) * 3 + ((n & 1) - (m & 1) + 1);
            s[n][m] = t * scale + table[ridx * 8 + head];
        }
    }

    float outd = 0.f;
#pragma unroll
    for (int n = 0; n < 4; n++) {
        float mx = fmaxf(fmaxf(s[n][0], s[n][1]), fmaxf(s[n][2], s[n][3]));
        float e0 = __expf(s[n][0] - mx);
        float e1 = __expf(s[n][1] - mx);
        float e2 = __expf(s[n][2] - mx);
        float e3 = __expf(s[n][3] - mx);
        float inv = 1.f / (e0 + e1 + e2 + e3);
        outd += (e0 * v[0] + e1 * v[1] + e2 * v[2] + e3 * v[3]) * inv;
    }
    int o = p * 512 + ctx * 256 + head * 32 + lane;
    split_bf16(outd * 0.25f, &g_mf_hi[o], &g_mf_lo[o]);
}

// ===========================================================================
// Fuse proj into merge; emit bf16 hi/lo planes for GEMM2 B.
// ===========================================================================
__global__ __launch_bounds__(512) void fuse_w_kernel(const float* __restrict__ mw,
                                                     const float* __restrict__ pw) {
    int d = blockIdx.x;
    int e = threadIdx.x;
    int eh = e & 255;
    int half = e >> 8;
    const float* mrow = mw + d * 512 + half * 256;
    float acc = 0.f;
#pragma unroll 4
    for (int cc = 0; cc < 256; cc++) acc += mrow[cc] * pw[cc * 256 + eh];
    split_bf16(acc, &g_wc_hi[d * 512 + e], &g_wc_lo[d * 512 + e]);
}

// One block per output d; 256 threads reduce over c.
__global__ __launch_bounds__(256) void fuse_bias_kernel(const float* __restrict__ mw,
                                                        const float* __restrict__ pb,
                                                        const float* __restrict__ mb) {
    __shared__ float red[8];
    int d = blockIdx.x;
    int t = threadIdx.x;
    float acc = pb[t] * (mw[d * 512 + t] + mw[d * 512 + 256 + t]);
    acc += __shfl_xor_sync(0xffffffffu, acc, 16);
    acc += __shfl_xor_sync(0xffffffffu, acc, 8);
    acc += __shfl_xor_sync(0xffffffffu, acc, 4);
    acc += __shfl_xor_sync(0xffffffffu, acc, 2);
    acc += __shfl_xor_sync(0xffffffffu, acc, 1);
    if ((t & 31) == 0) red[t >> 5] = acc;
    __syncthreads();
    if (t == 0) {
        float s = mb[d];
#pragma unroll
        for (int i = 0; i < 8; i++) s += red[i];
        g_biasf[d] = s;
    }
}

// ===========================================================================
// Launch
// ===========================================================================
extern "C" void kernel_launch(void* const* d_in, const int* in_sizes, int n_in,
                              void* d_out, int out_size) {
    const float* x     = (const float*)d_in[0];
    const float* uw    = (const float*)d_in[1];
    const float* ub    = (const float*)d_in[2];
    const float* qkvw  = (const float*)d_in[3];
    const float* qkvb  = (const float*)d_in[4];
    const float* table = (const float*)d_in[5];
    const float* pw    = (const float*)d_in[6];
    const float* pb    = (const float*)d_in[7];
    const float* mw    = (const float*)d_in[8];
    const float* mb    = (const float*)d_in[9];
    float* out = (float*)d_out;

    float* qkv;
    float* biasf;
    __nv_bfloat16 *uAh, *uAl, *wqh, *wql, *mfh, *mfl, *wch, *wcl;
    cudaGetSymbolAddress((void**)&qkv, g_qkv);
    cudaGetSymbolAddress((void**)&biasf, g_biasf);
    cudaGetSymbolAddress((void**)&uAh, g_uA_hi);
    cudaGetSymbolAddress((void**)&uAl, g_uA_lo);
    cudaGetSymbolAddress((void**)&wqh, g_wq_hi);
    cudaGetSymbolAddress((void**)&wql, g_wq_lo);
    cudaGetSymbolAddress((void**)&mfh, g_mf_hi);
    cudaGetSymbolAddress((void**)&mfl, g_mf_lo);
    cudaGetSymbolAddress((void**)&wch, g_wc_hi);
    cudaGetSymbolAddress((void**)&wcl, g_wc_lo);

    cudaFuncSetAttribute(bgemm_x2, cudaFuncAttributeMaxDynamicSharedMemorySize,
                         TB_SMEM);

    // prep kernels (cheap)
    wtrans_kernel<<<128, 256>>>(uw);
    wq_split_kernel<<<768, 256>>>(qkvw);
    fuse_w_kernel<<<512, 512>>>(mw, pw);
    fuse_bias_kernel<<<512, 256>>>(mw, pb, mb);

    // main chain
    conv_kernel<<<1024, 256>>>(x, ub);
    bgemm_x2<<<dim3(768 / 128, 8192 / 128), 256, TB_SMEM>>>(uAh, uAl, wqh, wql,
                                                            qkvb, qkv, 256, 768);
    attn_kernel<<<8192, 512>>>(table);
    bgemm_x2<<<dim3(512 / 128, 8192 / 128), 256, TB_SMEM>>>(mfh, mfl, wch, wcl,
                                                            biasf, out, 512, 512);
}